// round 8
// baseline (speedup 1.0000x reference)
#include <cuda_runtime.h>
#include <cstdint>
#include <cstddef>

#define TT 512
#define BB 256
#define HH 128
#define G3 384
#define MM (BB * TT)

// Scratch (device globals — no allocations allowed)
__device__ float g_gx[(size_t)MM * G3];     // [B*T, 384] input-side gates (reused per layer)
__device__ float g_h1[(size_t)MM * HH];     // [B*T, 128] layer-1 outputs
__device__ float g_hlast[BB * HH];          // [B, 128] final hidden of layer 2

typedef unsigned long long ull;

// ---------------- packed f32x2 helpers ----------------
__device__ __forceinline__ ull pack2(float x, float y) {
    ull r;
    asm("mov.b64 %0, {%1, %2};" : "=l"(r) : "f"(x), "f"(y));
    return r;
}
__device__ __forceinline__ void unpack2(ull v, float& x, float& y) {
    asm("mov.b64 {%0, %1}, %2;" : "=f"(x), "=f"(y) : "l"(v));
}
__device__ __forceinline__ void fma2(ull& acc, ull a, ull b) {
    asm("fma.rn.f32x2 %0, %1, %2, %0;" : "+l"(acc) : "l"(a), "l"(b));
}

__device__ __forceinline__ float sigmoid_f(float x) {
    return __fdividef(1.f, 1.f + __expf(-x));
}
__device__ __forceinline__ float tanh_f(float x) {
    return 1.f - __fdividef(2.f, 1.f + __expf(2.f * x));
}

// ---------------- gx GEMM: out[m,n] = sum_k A[m,k]*W[n,k] + bias[n] ----------------
// f32x2 packed along k: each accumulator holds two k-streams, reduced at the end.
// Tile: 128m x 64n, 256 threads (16x16), 8m x 4n per thread, K chunks of 32.
// Smem layout transposed to [kpair][row] float2 so operand loads are wide & natural.
template <bool GATHER>
__global__ __launch_bounds__(256) void gx_kernel(
    const int* __restrict__ xtok,   // [M] tokens (GATHER only)
    const float* __restrict__ emb,  // [V,128]   (GATHER only)
    const float* __restrict__ Ain,  // [M,128]   (!GATHER)
    const float* __restrict__ W,    // [384,128] layer slice
    const float* __restrict__ bias, // [384] layer slice
    float* __restrict__ outp)       // [M,384]
{
    __shared__ __align__(16) float2 As2[16][130];  // [kp][m], pad 2 to spread fill banks
    __shared__ __align__(16) float2 Bs2[16][66];   // [kp][n]

    const int tid = threadIdx.x;
    const int tx = tid & 15;        // n group
    const int ty = tid >> 4;        // m group
    const int m0g = blockIdx.x * 128;
    const int n0g = blockIdx.y * 64;

    ull c[8][4];
#pragma unroll
    for (int i = 0; i < 8; i++)
#pragma unroll
        for (int j = 0; j < 4; j++) c[i][j] = pack2(0.f, 0.f);

    for (int kc = 0; kc < HH; kc += 32) {
        // ---- A fill: 128 rows x 32 k = 1024 float4, 4 per thread ----
#pragma unroll
        for (int it = 0; it < 4; it++) {
            int f = tid + 256 * it;
            int m = f >> 3;          // 8 float4 per row
            int kq = f & 7;
            const float* arow;
            if (GATHER) {
                int tokv = __ldg(xtok + m0g + m);
                arow = emb + (size_t)tokv * HH;
            } else {
                arow = Ain + (size_t)(m0g + m) * HH;
            }
            float4 v = *reinterpret_cast<const float4*>(arow + kc + kq * 4);
            As2[kq * 2][m] = make_float2(v.x, v.y);
            As2[kq * 2 + 1][m] = make_float2(v.z, v.w);
        }
        // ---- B fill: 64 rows x 32 k = 512 float4, 2 per thread ----
#pragma unroll
        for (int it = 0; it < 2; it++) {
            int f = tid + 256 * it;
            int n = f >> 3;
            int kq = f & 7;
            float4 v = *reinterpret_cast<const float4*>(W + (size_t)(n0g + n) * HH + kc + kq * 4);
            Bs2[kq * 2][n] = make_float2(v.x, v.y);
            Bs2[kq * 2 + 1][n] = make_float2(v.z, v.w);
        }
        __syncthreads();

#pragma unroll
        for (int kp = 0; kp < 16; kp++) {
            ull a[8], b[4];
            const ulonglong2* ap = reinterpret_cast<const ulonglong2*>(&As2[kp][ty * 8]);
            ulonglong2 t0 = ap[0], t1 = ap[1], t2 = ap[2], t3 = ap[3];
            a[0] = t0.x; a[1] = t0.y; a[2] = t1.x; a[3] = t1.y;
            a[4] = t2.x; a[5] = t2.y; a[6] = t3.x; a[7] = t3.y;
            const ulonglong2* bp = reinterpret_cast<const ulonglong2*>(&Bs2[kp][tx * 4]);
            ulonglong2 u0 = bp[0], u1 = bp[1];
            b[0] = u0.x; b[1] = u0.y; b[2] = u1.x; b[3] = u1.y;
#pragma unroll
            for (int i = 0; i < 8; i++) {
                fma2(c[i][0], a[i], b[0]);
                fma2(c[i][1], a[i], b[1]);
                fma2(c[i][2], a[i], b[2]);
                fma2(c[i][3], a[i], b[3]);
            }
        }
        __syncthreads();
    }

    float4 bv = *reinterpret_cast<const float4*>(bias + n0g + tx * 4);
#pragma unroll
    for (int i = 0; i < 8; i++) {
        int m = m0g + ty * 8 + i;
        float lo, hi;
        float4 o;
        unpack2(c[i][0], lo, hi); o.x = lo + hi + bv.x;
        unpack2(c[i][1], lo, hi); o.y = lo + hi + bv.y;
        unpack2(c[i][2], lo, hi); o.z = lo + hi + bv.z;
        unpack2(c[i][3], lo, hi); o.w = lo + hi + bv.w;
        *reinterpret_cast<float4*>(outp + (size_t)m * G3 + n0g + tx * 4) = o;
    }
}

// ---------------- GRU recurrence: 2 samples per CTA, 384 threads ----------------
// Thread g owns gate row g: W_hh[g,:] in 64 packed f32x2 registers.
// h (both samples, k-paired) in smem as double2[64]:
//   float layout: [4*(j>>1) + 2*s + (j&1)]  (s=sample, j=hidden idx)
// Epilogue distributed over 256 threads: all gate groups publish pre-barrier,
// then thread u<256 does exactly one tanh + h-update for (s,j).
__global__ __launch_bounds__(384, 1) void gru_rec_kernel(
    const float* __restrict__ gx,    // [B,T,384]
    const float* __restrict__ Whh,   // [384,128] layer slice
    const float* __restrict__ bhh,   // [384] layer slice
    float* __restrict__ out_all,     // [B,T,128] or nullptr
    float* __restrict__ out_last)    // [B,128]   or nullptr
{
    __shared__ double2 sh_h[64];       // packed h for both samples
    __shared__ float sm_r[2][HH];
    __shared__ float sm_z[2][HH];
    __shared__ float2 sm_n[2][HH];     // (xn, hn_dot + bhh)

    const int g = threadIdx.x;
    const int s0 = blockIdx.x * 2;

    // This thread's W_hh row, packed over k-pairs
    ull wp[64];
    const float2* wrow = reinterpret_cast<const float2*>(Whh + (size_t)g * HH);
#pragma unroll
    for (int kp = 0; kp < 64; kp++) {
        float2 w = wrow[kp];
        wp[kp] = pack2(w.x, w.y);
    }
    const float bh = bhh[g];

    if (g < 256) reinterpret_cast<float*>(sh_h)[g] = 0.f;  // h0 = 0

    const float* gp0 = gx + (size_t)s0 * TT * G3 + g;
    const float* gp1 = gp0 + (size_t)TT * G3;
    float cur0 = gp0[0];
    float cur1 = gp1[0];

    __syncthreads();

    for (int t = 0; t < TT; t++) {
        // prefetch next step's gx while the dot product runs
        float nxt0 = 0.f, nxt1 = 0.f;
        if (t + 1 < TT) {
            nxt0 = gp0[(size_t)(t + 1) * G3];
            nxt1 = gp1[(size_t)(t + 1) * G3];
        }

        // gh = W_hh[g,:] . h  (both samples, 4 independent accumulator chains)
        ull a0 = pack2(0.f, 0.f), a1 = pack2(0.f, 0.f);
        ull a2 = pack2(0.f, 0.f), a3 = pack2(0.f, 0.f);
#pragma unroll
        for (int kp = 0; kp < 32; kp++) {
            double2 hv = sh_h[kp];
            fma2(a0, wp[kp], (ull)__double_as_longlong(hv.x));
            fma2(a1, wp[kp], (ull)__double_as_longlong(hv.y));
        }
#pragma unroll
        for (int kp = 32; kp < 64; kp++) {
            double2 hv = sh_h[kp];
            fma2(a2, wp[kp], (ull)__double_as_longlong(hv.x));
            fma2(a3, wp[kp], (ull)__double_as_longlong(hv.y));
        }
        float lo, hi, lo2, hi2;
        unpack2(a0, lo, hi);
        unpack2(a2, lo2, hi2);
        float d0 = (lo + hi) + (lo2 + hi2) + bh;
        unpack2(a1, lo, hi);
        unpack2(a3, lo2, hi2);
        float d1 = (lo + hi) + (lo2 + hi2) + bh;

        if (g < HH) {                       // r gates (warps 0-3)
            sm_r[0][g] = sigmoid_f(cur0 + d0);
            sm_r[1][g] = sigmoid_f(cur1 + d1);
        } else if (g < 2 * HH) {            // z gates (warps 4-7)
            int j = g - HH;
            sm_z[0][j] = sigmoid_f(cur0 + d0);
            sm_z[1][j] = sigmoid_f(cur1 + d1);
        } else {                            // n gates (warps 8-11): publish (xn, hn)
            int j = g - 2 * HH;
            sm_n[0][j] = make_float2(cur0, d0);
            sm_n[1][j] = make_float2(cur1, d1);
        }
        __syncthreads();

        // Distributed epilogue: one (sample, j) per thread, 8 warps busy
        if (g < 256) {
            int s = g >> 7;
            int j = g & 127;
            float r = sm_r[s][j];
            float z = sm_z[s][j];
            float2 nd = sm_n[s][j];
            float* f = reinterpret_cast<float*>(sh_h);
            int pos = 4 * (j >> 1) + 2 * s + (j & 1);
            float hprev = f[pos];                 // only this thread touches pos here
            float n = tanh_f(nd.x + r * nd.y);
            float h = n + z * (hprev - n);        // (1-z)*n + z*hprev
            f[pos] = h;
            if (out_all) out_all[((size_t)(s0 + s) * TT + t) * HH + j] = h;
            if (out_last && t == TT - 1) out_last[(s0 + s) * HH + j] = h;
        }
        cur0 = nxt0;
        cur1 = nxt1;
        __syncthreads();
    }
}

// ---------------- FC head ----------------
__global__ __launch_bounds__(32) void fc_kernel(
    const float* __restrict__ hlast,  // [B,128]
    const float* __restrict__ fw,     // [3,128]
    const float* __restrict__ fb,     // [3]
    float* __restrict__ outp)         // [B,3]
{
    const int b = blockIdx.x;
    const int lane = threadIdx.x;
    float hv[4];
#pragma unroll
    for (int i = 0; i < 4; i++) {
        float v = hlast[b * HH + lane + 32 * i];
        hv[i] = v > 0.f ? v : 0.f;
    }
#pragma unroll
    for (int o = 0; o < 3; o++) {
        float acc = 0.f;
#pragma unroll
        for (int i = 0; i < 4; i++) acc += hv[i] * fw[o * HH + lane + 32 * i];
#pragma unroll
        for (int d = 16; d; d >>= 1) acc += __shfl_xor_sync(0xffffffffu, acc, d);
        if (lane == 0) outp[b * 3 + o] = acc + fb[o];
    }
}

// ---------------- launch ----------------
extern "C" void kernel_launch(void* const* d_in, const int* in_sizes, int n_in,
                              void* d_out, int out_size) {
    const int* x = (const int*)d_in[0];        // [256,512] int32
    const float* emb = (const float*)d_in[1];  // [29275,128]
    const float* W_ih = (const float*)d_in[2]; // [2,384,128]
    const float* W_hh = (const float*)d_in[3]; // [2,384,128]
    const float* b_ih = (const float*)d_in[4]; // [2,384]
    const float* b_hh = (const float*)d_in[5]; // [2,384]
    const float* fc_w = (const float*)d_in[6]; // [3,128]
    const float* fc_b = (const float*)d_in[7]; // [3]
    float* out = (float*)d_out;                // [256,3]

    float *gx, *h1, *hl;
    cudaGetSymbolAddress((void**)&gx, g_gx);
    cudaGetSymbolAddress((void**)&h1, g_h1);
    cudaGetSymbolAddress((void**)&hl, g_hlast);

    dim3 gg(MM / 128, G3 / 64);

    // Layer 1
    gx_kernel<true><<<gg, 256>>>(x, emb, nullptr, W_ih, b_ih, gx);
    gru_rec_kernel<<<BB / 2, 384>>>(gx, W_hh, b_hh, h1, nullptr);
    // Layer 2
    gx_kernel<false><<<gg, 256>>>(nullptr, nullptr, h1, W_ih + G3 * HH, b_ih + G3, gx);
    gru_rec_kernel<<<BB / 2, 384>>>(gx, W_hh + G3 * HH, b_hh + G3, nullptr, hl);
    // Head
    fc_kernel<<<BB, 32>>>(hl, fc_w, fc_b, out);
}